// round 2
// baseline (speedup 1.0000x reference)
#include <cuda_runtime.h>
#include <math.h>

#define BATCH 8
#define TK    512
#define FDIM  32
#define NTQ   128
#define EDIM  128
#define HDIM  128

// ---------------- scratch (static device memory; no allocations) ----------------
__device__ float g_q[NTQ * EDIM];            // 64 KB
__device__ float g_k[BATCH * TK * EDIM];     // 2 MB
__device__ float g_s[BATCH * NTQ * TK];      // 2 MB raw scores
__device__ float g_att[BATCH * NTQ * 64];    // attention output channels
__device__ float g_gi[BATCH * NTQ * 384];    // precomputed GRU input gates
__device__ float g_hl[BATCH * HDIM];         // GRU last hidden

__device__ __forceinline__ float wsum(float v) {
#pragma unroll
    for (int o = 16; o; o >>= 1) v += __shfl_xor_sync(0xffffffffu, v, o);
    return v;
}
__device__ __forceinline__ float wmax(float v) {
#pragma unroll
    for (int o = 16; o; o >>= 1) v = fmaxf(v, __shfl_xor_sync(0xffffffffu, v, o));
    return v;
}

// ---------------------------------------------------------------------------
// Kernel 1/2: time embedding -> linear proj -> LayerNorm.
// 32 rows per block, 128 threads. Thread e keeps W row e in registers,
// embeddings live in smem (broadcast reads).
// toK==0 -> write g_q (times==nullptr -> linspace(0,1,128)); toK==1 -> g_k.
// ---------------------------------------------------------------------------
__global__ __launch_bounds__(128) void k_embed_proj_ln(
    const float* __restrict__ times,
    const float* __restrict__ pw, const float* __restrict__ pb,
    const float* __restrict__ lw, const float* __restrict__ lb,
    const float* __restrict__ W,  const float* __restrict__ bias,
    const float* __restrict__ gamma, const float* __restrict__ beta,
    int toK)
{
    __shared__ float emb[32 * 128];
    __shared__ float pm[32 * 132];
    const int tid = threadIdx.x;
    const int r0 = blockIdx.x * 32;
    float* outp = toK ? g_k : g_q;

    const float lwv = lw[0], lbv = lb[0];
    for (int i = tid; i < 32 * 128; i += 128) {
        int r = i >> 7, e = i & 127;
        float t = times ? times[r0 + r] : (float)(r0 + r) * (1.0f / 127.0f);
        float v = (e == 0) ? (t * lwv + lbv) : sinf(t * pw[e - 1] + pb[e - 1]);
        emb[i] = v;
    }
    __syncthreads();

    // W row (tid) into registers
    float w[128];
    {
        const float4* wr = (const float4*)(W + tid * 128);
#pragma unroll
        for (int i = 0; i < 32; i++) {
            float4 v = wr[i];
            w[4 * i] = v.x; w[4 * i + 1] = v.y; w[4 * i + 2] = v.z; w[4 * i + 3] = v.w;
        }
    }
    const float bv = bias[tid];

    for (int r = 0; r < 32; r++) {
        const float4* er = (const float4*)(emb + r * 128);
        float acc = bv;
#pragma unroll
        for (int i = 0; i < 32; i++) {
            float4 e4 = er[i];
            acc += e4.x * w[4 * i] + e4.y * w[4 * i + 1] + e4.z * w[4 * i + 2] + e4.w * w[4 * i + 3];
        }
        pm[r * 132 + tid] = acc;
    }
    __syncthreads();

    // per-row LayerNorm (4 warps x 8 rows)
    const int wid = tid >> 5, lane = tid & 31;
    for (int rr = 0; rr < 8; rr++) {
        int r = wid * 8 + rr;
        float v0 = pm[r * 132 + lane];
        float v1 = pm[r * 132 + lane + 32];
        float v2 = pm[r * 132 + lane + 64];
        float v3 = pm[r * 132 + lane + 96];
        float mean = wsum(v0 + v1 + v2 + v3) * (1.0f / 128.0f);
        float d0 = v0 - mean, d1 = v1 - mean, d2 = v2 - mean, d3 = v3 - mean;
        float var = wsum(d0 * d0 + d1 * d1 + d2 * d2 + d3 * d3) * (1.0f / 128.0f);
        float rs = rsqrtf(var + 1e-5f);
        float* orow = outp + (r0 + r) * 128;
        orow[lane]      = d0 * rs * gamma[lane]      + beta[lane];
        orow[lane + 32] = d1 * rs * gamma[lane + 32] + beta[lane + 32];
        orow[lane + 64] = d2 * rs * gamma[lane + 64] + beta[lane + 64];
        orow[lane + 96] = d3 * rs * gamma[lane + 96] + beta[lane + 96];
    }
}

// ---------------------------------------------------------------------------
// Kernel 3: scores[b,nt,t] = q[nt,:] . k[b,t,:] / sqrt(E)
// grid: B*16 blocks, each = (b, 8 nt rows). 256 threads, k tiles of 64 in smem.
// ---------------------------------------------------------------------------
__global__ __launch_bounds__(256) void k_scores()
{
    __shared__ float sQ[8 * 128];
    __shared__ float sK[64 * 132];
    const int tid = threadIdx.x;
    const int b = blockIdx.x >> 4;
    const int nt0 = (blockIdx.x & 15) * 8;
    const float scale = 0.08838834764831845f;  // 1/sqrt(128)

    // load 8 q rows (contiguous 1024 floats)
    ((float4*)sQ)[tid] = ((const float4*)(g_q + nt0 * 128))[tid];

    const int tl = tid & 63;
    const int ntp = tid >> 6;  // 0..3 -> nt pair

    for (int kt = 0; kt < 8; kt++) {
        __syncthreads();
        for (int i = tid; i < 2048; i += 256) {
            int row = i >> 5, c4 = i & 31;
            float4 v = ((const float4*)(g_k + ((b * TK) + kt * 64 + row) * 128))[c4];
            *(float4*)(sK + row * 132 + c4 * 4) = v;
        }
        __syncthreads();

        float a0 = 0.f, a1 = 0.f;
        const float* q0 = sQ + (ntp * 2) * 128;
        const float* q1 = q0 + 128;
        const float* kr = sK + tl * 132;
#pragma unroll
        for (int i = 0; i < 32; i++) {
            float4 kv = *(const float4*)(kr + 4 * i);
            float4 qa = *(const float4*)(q0 + 4 * i);
            float4 qb = *(const float4*)(q1 + 4 * i);
            a0 += qa.x * kv.x + qa.y * kv.y + qa.z * kv.z + qa.w * kv.w;
            a1 += qb.x * kv.x + qb.y * kv.y + qb.z * kv.z + qb.w * kv.w;
        }
        int t = kt * 64 + tl;
        g_s[(b * NTQ + nt0 + ntp * 2) * TK + t]     = a0 * scale;
        g_s[(b * NTQ + nt0 + ntp * 2 + 1) * TK + t] = a1 * scale;
    }
}

// ---------------------------------------------------------------------------
// Kernel 4: per-channel masked attention.
// grid: B*16 blocks (b, 8 nt). 256 threads.
// Phase 1: per-nt row max + e=exp(s-max) into smem (shared by all 32 channels).
// Phase 2: thread (c,nt): denom = sum e*m, numer = sum e*x_masked.
//          att_x = numer/denom (0 if denom==0), att_m = denom>0 ? 1 : 0.
// ---------------------------------------------------------------------------
__global__ __launch_bounds__(256) void k_attn(
    const float* __restrict__ input, const float* __restrict__ mask)
{
    __shared__ float sE[8 * 516];
    const int tid = threadIdx.x;
    const int b = blockIdx.x >> 4;
    const int nt0 = (blockIdx.x & 15) * 8;

    // Phase 1: warp r handles nt row r
    {
        int r = tid >> 5, lane = tid & 31;
        const float* srow = g_s + (b * NTQ + nt0 + r) * TK;
        float mx = -1e30f;
#pragma unroll
        for (int k = 0; k < 16; k++) mx = fmaxf(mx, srow[lane + 32 * k]);
        mx = wmax(mx);
#pragma unroll
        for (int k = 0; k < 16; k++) {
            int t = lane + 32 * k;
            sE[r * 516 + t] = __expf(srow[t] - mx);
        }
    }
    __syncthreads();

    // Phase 2
    const int c = tid >> 3;   // 0..31
    const int nt = tid & 7;   // 0..7
    const float4* mrow = (const float4*)(mask  + (b * FDIM + c) * TK);
    const float4* xrow = (const float4*)(input + (b * FDIM + c) * TK);
    const float* erow = sE + nt * 516;

    float den = 0.f, num = 0.f;
#pragma unroll 4
    for (int t4 = 0; t4 < 128; t4++) {
        float4 e4 = *(const float4*)(erow + 4 * t4);
        float4 mk = mrow[t4];
        float4 xv = xrow[t4];
        float m0 = (mk.x == 0.f) ? 1.f : 0.f;
        float m1 = (mk.y == 0.f) ? 1.f : 0.f;
        float m2 = (mk.z == 0.f) ? 1.f : 0.f;
        float m3 = (mk.w == 0.f) ? 1.f : 0.f;
        den += e4.x * m0 + e4.y * m1 + e4.z * m2 + e4.w * m3;
        num += e4.x * m0 * xv.x + e4.y * m1 * xv.y + e4.z * m2 * xv.z + e4.w * m3 * xv.w;
    }
    float ax = (den > 0.f) ? (num / den) : 0.f;
    float am = (den > 0.f) ? 1.f : 0.f;
    float* arow = g_att + (b * NTQ + nt0 + nt) * 64;
    arow[c]      = ax;
    arow[c + 32] = am;
}

// ---------------------------------------------------------------------------
// Kernel 5: attn LN -> out proj -> LN -> gi = out @ Wih^T + bih (GRU input gates).
// grid: B*8 blocks (b, 16 nt rows), 384 threads.
// ---------------------------------------------------------------------------
__global__ __launch_bounds__(384, 1) void k_post(
    const float* __restrict__ attn_g, const float* __restrict__ attn_b,
    const float* __restrict__ out_w,  const float* __restrict__ out_b,
    const float* __restrict__ out_g,  const float* __restrict__ out_be,
    const float* __restrict__ wih,    const float* __restrict__ bih)
{
    __shared__ float satt[16 * 64];
    __shared__ float x2[16 * 64];
    __shared__ float ov[16 * 128];
    const int tid = threadIdx.x;
    const int b = blockIdx.x >> 3;
    const int nt0 = (blockIdx.x & 7) * 16;
    const int wid = tid >> 5, lane = tid & 31;

    for (int i = tid; i < 1024; i += 384)
        satt[i] = g_att[(b * NTQ + nt0) * 64 + i];
    __syncthreads();

    // Phase A: attn LayerNorm per row (64 channels); warps 0..7 x 2 rows
    if (wid < 8) {
        for (int rr = 0; rr < 2; rr++) {
            int r = wid * 2 + rr;
            float v0 = satt[r * 64 + lane];
            float v1 = satt[r * 64 + lane + 32];
            float mean = wsum(v0 + v1) * (1.0f / 64.0f);
            float d0 = v0 - mean, d1 = v1 - mean;
            float var = wsum(d0 * d0 + d1 * d1) * (1.0f / 64.0f);
            float rs = rsqrtf(var + 1e-5f);
            x2[r * 64 + lane]      = d0 * rs * attn_g[lane]      + attn_b[lane];
            x2[r * 64 + lane + 32] = d1 * rs * attn_g[lane + 32] + attn_b[lane + 32];
        }
    }
    __syncthreads();

    // Phase B: out projection, out_w row in registers
    if (tid < 256) {
        int h = tid & 127, half = tid >> 7;
        float wo[64];
        const float4* wrow = (const float4*)(out_w + h * 64);
#pragma unroll
        for (int i = 0; i < 16; i++) {
            float4 v = wrow[i];
            wo[4 * i] = v.x; wo[4 * i + 1] = v.y; wo[4 * i + 2] = v.z; wo[4 * i + 3] = v.w;
        }
        float ob = out_b[h];
        for (int rr = 0; rr < 8; rr++) {
            int r = half * 8 + rr;
            float acc = ob;
#pragma unroll
            for (int cc = 0; cc < 64; cc++) acc += x2[r * 64 + cc] * wo[cc];
            ov[r * 128 + h] = acc;
        }
    }
    __syncthreads();

    // LN on ov rows (128 wide); warps 0..7 x 2 rows
    if (wid < 8) {
        for (int rr = 0; rr < 2; rr++) {
            int r = wid * 2 + rr;
            float v0 = ov[r * 128 + lane];
            float v1 = ov[r * 128 + lane + 32];
            float v2 = ov[r * 128 + lane + 64];
            float v3 = ov[r * 128 + lane + 96];
            float mean = wsum(v0 + v1 + v2 + v3) * (1.0f / 128.0f);
            float d0 = v0 - mean, d1 = v1 - mean, d2 = v2 - mean, d3 = v3 - mean;
            float var = wsum(d0 * d0 + d1 * d1 + d2 * d2 + d3 * d3) * (1.0f / 128.0f);
            float rs = rsqrtf(var + 1e-5f);
            ov[r * 128 + lane]      = d0 * rs * out_g[lane]      + out_be[lane];
            ov[r * 128 + lane + 32] = d1 * rs * out_g[lane + 32] + out_be[lane + 32];
            ov[r * 128 + lane + 64] = d2 * rs * out_g[lane + 64] + out_be[lane + 64];
            ov[r * 128 + lane + 96] = d3 * rs * out_g[lane + 96] + out_be[lane + 96];
        }
    }
    __syncthreads();

    // Phase C: gi rows; thread j keeps Wih row in registers
    {
        float w[128];
        const float4* wrow = (const float4*)(wih + tid * 128);
#pragma unroll
        for (int i = 0; i < 32; i++) {
            float4 v = wrow[i];
            w[4 * i] = v.x; w[4 * i + 1] = v.y; w[4 * i + 2] = v.z; w[4 * i + 3] = v.w;
        }
        float bj = bih[tid];
        for (int r = 0; r < 16; r++) {
            const float4* h4 = (const float4*)(ov + r * 128);
            float acc = bj;
#pragma unroll
            for (int i = 0; i < 32; i++) {
                float4 hv = h4[i];
                acc += hv.x * w[4 * i] + hv.y * w[4 * i + 1] + hv.z * w[4 * i + 2] + hv.w * w[4 * i + 3];
            }
            g_gi[(b * NTQ + nt0 + r) * 384 + tid] = acc;
        }
    }
}

// ---------------------------------------------------------------------------
// Kernel 6: GRU recurrence, 8 blocks (1/batch), 384 threads.
// Thread j holds Whh row j in registers; h broadcast from smem.
// gi precomputed. Torch gate order r,z,n.
// ---------------------------------------------------------------------------
__global__ __launch_bounds__(384, 1) void k_gru(
    const float* __restrict__ whh, const float* __restrict__ bhh)
{
    __shared__ float sh[128];
    __shared__ float s1[384];
    __shared__ float sn[128];   // gh for n gate
    __shared__ float sgn[128];  // gi for n gate
    const int j = threadIdx.x;
    const int b = blockIdx.x;

    float w[128];
    {
        const float4* wr = (const float4*)(whh + j * 128);
#pragma unroll
        for (int i = 0; i < 32; i++) {
            float4 v = wr[i];
            w[4 * i] = v.x; w[4 * i + 1] = v.y; w[4 * i + 2] = v.z; w[4 * i + 3] = v.w;
        }
    }
    const float bj = bhh[j];
    if (j < 128) sh[j] = 0.f;
    __syncthreads();

    for (int t = 0; t < NTQ; t++) {
        float acc = bj;
        const float4* h4 = (const float4*)sh;
#pragma unroll
        for (int i = 0; i < 32; i++) {
            float4 hv = h4[i];
            acc += hv.x * w[4 * i] + hv.y * w[4 * i + 1] + hv.z * w[4 * i + 2] + hv.w * w[4 * i + 3];
        }
        float giv = g_gi[(b * NTQ + t) * 384 + j];
        s1[j] = acc + giv;
        if (j >= 256) { sn[j - 256] = acc; sgn[j - 256] = giv; }
        __syncthreads();
        if (j < 128) {
            float r = 1.f / (1.f + __expf(-s1[j]));
            float z = 1.f / (1.f + __expf(-s1[j + 128]));
            float n = tanhf(sgn[j] + r * sn[j]);
            sh[j] = (1.f - z) * n + z * sh[j];
        }
        __syncthreads();
    }
    if (j < 128) g_hl[b * 128 + j] = sh[j];
}

// ---------------------------------------------------------------------------
// Kernel 7: classifier MLP -> logits (B, 2)
// ---------------------------------------------------------------------------
__global__ __launch_bounds__(128) void k_cls(
    const float* __restrict__ c1w, const float* __restrict__ c1b,
    const float* __restrict__ c2w, const float* __restrict__ c2b,
    const float* __restrict__ c3w, const float* __restrict__ c3b,
    float* __restrict__ out)
{
    __shared__ float a[128];
    __shared__ float bb[128];
    const int tid = threadIdx.x;
    const int b = blockIdx.x;

    a[tid] = g_hl[b * 128 + tid];
    __syncthreads();
    {
        float acc = c1b[tid];
        const float4* wr = (const float4*)(c1w + tid * 128);
        const float4* h4 = (const float4*)a;
#pragma unroll
        for (int i = 0; i < 32; i++) {
            float4 wv = wr[i]; float4 hv = h4[i];
            acc += hv.x * wv.x + hv.y * wv.y + hv.z * wv.z + hv.w * wv.w;
        }
        bb[tid] = fmaxf(acc, 0.f);
    }
    __syncthreads();
    {
        float acc = c2b[tid];
        const float4* wr = (const float4*)(c2w + tid * 128);
        const float4* h4 = (const float4*)bb;
#pragma unroll
        for (int i = 0; i < 32; i++) {
            float4 wv = wr[i]; float4 hv = h4[i];
            acc += hv.x * wv.x + hv.y * wv.y + hv.z * wv.z + hv.w * wv.w;
        }
        a[tid] = fmaxf(acc, 0.f);
    }
    __syncthreads();
    if (tid < 32) {
        for (int s = 0; s < 2; s++) {
            float p = 0.f;
#pragma unroll
            for (int k = 0; k < 4; k++)
                p += a[tid + 32 * k] * c3w[s * 128 + tid + 32 * k];
            p = wsum(p);
            if (tid == 0) out[b * 2 + s] = p + c3b[s];
        }
    }
}

// ---------------------------------------------------------------------------
extern "C" void kernel_launch(void* const* d_in, const int* in_sizes, int n_in,
                              void* d_out, int out_size)
{
    const float* input      = (const float*)d_in[0];
    const float* mask       = (const float*)d_in[1];
    const float* timesteps  = (const float*)d_in[2];
    const float* periodic_w = (const float*)d_in[3];
    const float* periodic_b = (const float*)d_in[4];
    const float* lin_w      = (const float*)d_in[5];
    const float* lin_b      = (const float*)d_in[6];
    const float* q_w  = (const float*)d_in[7];
    const float* q_b  = (const float*)d_in[8];
    const float* q_g  = (const float*)d_in[9];
    const float* q_be = (const float*)d_in[10];
    const float* k_w  = (const float*)d_in[11];
    const float* k_b  = (const float*)d_in[12];
    const float* k_g  = (const float*)d_in[13];
    const float* k_be = (const float*)d_in[14];
    const float* attn_g = (const float*)d_in[15];
    const float* attn_b = (const float*)d_in[16];
    const float* out_w  = (const float*)d_in[17];
    const float* out_b  = (const float*)d_in[18];
    const float* out_g  = (const float*)d_in[19];
    const float* out_be = (const float*)d_in[20];
    const float* gru_wih = (const float*)d_in[21];
    const float* gru_whh = (const float*)d_in[22];
    const float* gru_bih = (const float*)d_in[23];
    const float* gru_bhh = (const float*)d_in[24];
    const float* c1_w = (const float*)d_in[25];
    const float* c1_b = (const float*)d_in[26];
    const float* c2_w = (const float*)d_in[27];
    const float* c2_b = (const float*)d_in[28];
    const float* c3_w = (const float*)d_in[29];
    const float* c3_b = (const float*)d_in[30];
    float* out = (float*)d_out;

    // query path: 128 rows of linspace(0,1,128)
    k_embed_proj_ln<<<4, 128>>>(nullptr, periodic_w, periodic_b, lin_w, lin_b,
                                q_w, q_b, q_g, q_be, /*toK=*/0);
    // key path: 8*512 rows of timesteps
    k_embed_proj_ln<<<128, 128>>>(timesteps, periodic_w, periodic_b, lin_w, lin_b,
                                  k_w, k_b, k_g, k_be, /*toK=*/1);
    k_scores<<<128, 256>>>();
    k_attn<<<128, 256>>>(input, mask);
    k_post<<<64, 384>>>(attn_g, attn_b, out_w, out_b, out_g, out_be,
                        gru_wih, gru_bih);
    k_gru<<<8, 384>>>(gru_whh, gru_bhh);
    k_cls<<<8, 128>>>(c1_w, c1_b, c2_w, c2_b, c3_w, c3_b, out);
    (void)in_sizes; (void)n_in; (void)out_size;
}

// round 4
// speedup vs baseline: 1.2848x; 1.2848x over previous
#include <cuda_runtime.h>
#include <math.h>

#define BATCH 8
#define TK    512
#define FDIM  32
#define NTQ   128
#define EDIM  128
#define HDIM  128

typedef unsigned long long u64;

// ---------------- scratch (static device memory; no allocations) ----------------
__device__ float g_q[NTQ * EDIM];
__device__ float g_k[BATCH * TK * EDIM];
__device__ float g_att[BATCH * NTQ * 64];
__device__ float g_gi[BATCH * NTQ * 384];
__device__ float g_hl[BATCH * HDIM];

__device__ __forceinline__ float wsum(float v) {
#pragma unroll
    for (int o = 16; o; o >>= 1) v += __shfl_xor_sync(0xffffffffu, v, o);
    return v;
}
__device__ __forceinline__ float wmax(float v) {
#pragma unroll
    for (int o = 16; o; o >>= 1) v = fmaxf(v, __shfl_xor_sync(0xffffffffu, v, o));
    return v;
}

// packed f32x2 FMA (FFMA2) — 2 MACs per issue slot; PTX-only on sm_103a
__device__ __forceinline__ u64 ffma2(u64 a, u64 b, u64 c) {
    u64 d;
    asm("fma.rn.f32x2 %0, %1, %2, %3;" : "=l"(d) : "l"(a), "l"(b), "l"(c));
    return d;
}
__device__ __forceinline__ float f2sum(u64 a) {
    float2 v = *(float2*)&a;
    return v.x + v.y;
}

// ---------------------------------------------------------------------------
// Kernel 1: time embedding -> proj -> LN for BOTH q (blocks 0..3) and k (4..131).
// 32 rows/block, 128 threads; thread e keeps W row e in registers (as f32x2).
// ---------------------------------------------------------------------------
__global__ __launch_bounds__(128) void k_embed(
    const float* __restrict__ times,
    const float* __restrict__ pw, const float* __restrict__ pb,
    const float* __restrict__ lw, const float* __restrict__ lb,
    const float* __restrict__ qW, const float* __restrict__ qbias,
    const float* __restrict__ qg, const float* __restrict__ qbe,
    const float* __restrict__ kW, const float* __restrict__ kbias,
    const float* __restrict__ kg, const float* __restrict__ kbe)
{
    __shared__ float emb[32 * 128];
    __shared__ float pm[32 * 132];
    const int tid = threadIdx.x;
    const bool isQ = blockIdx.x < 4;
    const int r0 = isQ ? blockIdx.x * 32 : (blockIdx.x - 4) * 32;
    float* outp = isQ ? g_q : g_k;
    const float* W     = isQ ? qW : kW;
    const float* bias  = isQ ? qbias : kbias;
    const float* gamma = isQ ? qg : kg;
    const float* beta  = isQ ? qbe : kbe;

    const float lwv = lw[0], lbv = lb[0];
    for (int i = tid; i < 32 * 128; i += 128) {
        int r = i >> 7, e = i & 127;
        float t = isQ ? (float)(r0 + r) * (1.0f / 127.0f) : times[r0 + r];
        float v = (e == 0) ? (t * lwv + lbv) : __sinf(t * pw[e - 1] + pb[e - 1]);
        emb[i] = v;
    }
    __syncthreads();

    u64 w2[64];
    {
        const ulonglong2* wr = (const ulonglong2*)(W + tid * 128);
#pragma unroll
        for (int i = 0; i < 32; i++) { ulonglong2 v = wr[i]; w2[2 * i] = v.x; w2[2 * i + 1] = v.y; }
    }
    const float bv = bias[tid];

    for (int r = 0; r < 32; r++) {
        const ulonglong2* er = (const ulonglong2*)(emb + r * 128);
        u64 a0 = 0, a1 = 0, a2 = 0, a3 = 0;
#pragma unroll
        for (int i = 0; i < 16; i++) {
            ulonglong2 e0 = er[2 * i], e1 = er[2 * i + 1];
            a0 = ffma2(w2[4 * i],     e0.x, a0);
            a1 = ffma2(w2[4 * i + 1], e0.y, a1);
            a2 = ffma2(w2[4 * i + 2], e1.x, a2);
            a3 = ffma2(w2[4 * i + 3], e1.y, a3);
        }
        pm[r * 132 + tid] = bv + f2sum(a0) + f2sum(a1) + f2sum(a2) + f2sum(a3);
    }
    __syncthreads();

    const int wid = tid >> 5, lane = tid & 31;
    for (int rr = 0; rr < 8; rr++) {
        int r = wid * 8 + rr;
        float v0 = pm[r * 132 + lane];
        float v1 = pm[r * 132 + lane + 32];
        float v2 = pm[r * 132 + lane + 64];
        float v3 = pm[r * 132 + lane + 96];
        float mean = wsum(v0 + v1 + v2 + v3) * (1.0f / 128.0f);
        float d0 = v0 - mean, d1 = v1 - mean, d2 = v2 - mean, d3 = v3 - mean;
        float var = wsum(d0 * d0 + d1 * d1 + d2 * d2 + d3 * d3) * (1.0f / 128.0f);
        float rs = rsqrtf(var + 1e-5f);
        float* orow = outp + (r0 + r) * 128;
        orow[lane]      = d0 * rs * gamma[lane]      + beta[lane];
        orow[lane + 32] = d1 * rs * gamma[lane + 32] + beta[lane + 32];
        orow[lane + 64] = d2 * rs * gamma[lane + 64] + beta[lane + 64];
        orow[lane + 96] = d3 * rs * gamma[lane + 96] + beta[lane + 96];
    }
}

// ---------------------------------------------------------------------------
// Kernel 2: FUSED scores + per-channel masked attention.
// grid: B*16 blocks (b, 8 nt rows), 512 threads, dynamic smem.
// smem: sQ[8*128] | sK[128*132] | sE[8*516]
// ---------------------------------------------------------------------------
#define SATTN_SMEM ((8 * 128 + 128 * 132 + 8 * 516) * 4)

__global__ __launch_bounds__(512) void k_sattn(
    const float* __restrict__ input, const float* __restrict__ mask)
{
    extern __shared__ float sm[];
    float* sQ = sm;                  // 1024
    float* sK = sQ + 8 * 128;        // 128*132
    float* sE = sK + 128 * 132;      // 8*516

    const int tid = threadIdx.x;
    const int b = blockIdx.x >> 4;
    const int nt0 = (blockIdx.x & 15) * 8;
    const float scale = 0.08838834764831845f;  // 1/sqrt(128)

    if (tid < 256)
        ((float4*)sQ)[tid] = ((const float4*)(g_q + nt0 * 128))[tid];

    const int tl = tid & 127;     // k row within tile
    const int ntp = tid >> 7;     // 0..3 -> pair of nt rows

    for (int kt = 0; kt < 4; kt++) {
        __syncthreads();
        // load 128 k rows
#pragma unroll
        for (int i = 0; i < 8; i++) {
            int idx = tid + i * 512;          // 0..4095 float4s
            int row = idx >> 5, c4 = idx & 31;
            float4 v = ((const float4*)(g_k + ((b * TK) + kt * 128 + row) * 128))[c4];
            *(float4*)(sK + row * 132 + c4 * 4) = v;
        }
        __syncthreads();

        const ulonglong2* kr = (const ulonglong2*)(sK + tl * 132);
        const ulonglong2* q0 = (const ulonglong2*)(sQ + (ntp * 2) * 128);
        const ulonglong2* q1 = q0 + 32;   // next 128-float row
        u64 a00 = 0, a01 = 0, a10 = 0, a11 = 0;
#pragma unroll
        for (int i = 0; i < 32; i++) {     // 32 x 4 floats = full 128-dim dot
            ulonglong2 kv = kr[i];
            ulonglong2 qa = q0[i];
            ulonglong2 qb = q1[i];
            a00 = ffma2(qa.x, kv.x, a00);
            a01 = ffma2(qa.y, kv.y, a01);
            a10 = ffma2(qb.x, kv.x, a10);
            a11 = ffma2(qb.y, kv.y, a11);
        }
        int t = kt * 128 + tl;
        sE[(ntp * 2) * 516 + t]     = (f2sum(a00) + f2sum(a01)) * scale;
        sE[(ntp * 2 + 1) * 516 + t] = (f2sum(a10) + f2sum(a11)) * scale;
    }
    __syncthreads();

    // per-nt-row max + exp (warp r handles row r)
    {
        int wid = tid >> 5, lane = tid & 31;
        if (wid < 8) {
            float* erow = sE + wid * 516;
            float mx = -1e30f;
#pragma unroll
            for (int k = 0; k < 16; k++) mx = fmaxf(mx, erow[lane + 32 * k]);
            mx = wmax(mx);
#pragma unroll
            for (int k = 0; k < 16; k++) {
                int t = lane + 32 * k;
                erow[t] = __expf(erow[t] - mx);
            }
        }
    }
    __syncthreads();

    // phase 2: thread (c, nt, half) accumulates over 256 t values
    const int c = tid >> 4;          // 0..31
    const int nt = (tid >> 1) & 7;   // 0..7
    const int half = tid & 1;        // 0..1
    const float4* mrow = (const float4*)(mask  + (b * FDIM + c) * TK + half * 256);
    const float4* xrow = (const float4*)(input + (b * FDIM + c) * TK + half * 256);
    const float* erow = sE + nt * 516 + half * 256;

    float den = 0.f, num = 0.f;
#pragma unroll 4
    for (int t4 = 0; t4 < 64; t4++) {
        float4 e4 = *(const float4*)(erow + 4 * t4);
        float4 mk = mrow[t4];
        float4 xv = xrow[t4];
        float m0 = (mk.x == 0.f) ? 1.f : 0.f;
        float m1 = (mk.y == 0.f) ? 1.f : 0.f;
        float m2 = (mk.z == 0.f) ? 1.f : 0.f;
        float m3 = (mk.w == 0.f) ? 1.f : 0.f;
        den += e4.x * m0 + e4.y * m1 + e4.z * m2 + e4.w * m3;
        num += e4.x * m0 * xv.x + e4.y * m1 * xv.y + e4.z * m2 * xv.z + e4.w * m3 * xv.w;
    }
    den += __shfl_xor_sync(0xffffffffu, den, 1);
    num += __shfl_xor_sync(0xffffffffu, num, 1);
    if (half == 0) {
        float ax = (den > 0.f) ? (num / den) : 0.f;
        float am = (den > 0.f) ? 1.f : 0.f;
        float* arow = g_att + (b * NTQ + nt0 + nt) * 64;
        arow[c]      = ax;
        arow[c + 32] = am;
    }
}

// ---------------------------------------------------------------------------
// Kernel 3: attn LN -> out proj -> LN -> gi = out @ Wih^T + bih
// grid: B*8 blocks (b, 16 nt rows), 384 threads.
// ---------------------------------------------------------------------------
__global__ __launch_bounds__(384, 1) void k_post(
    const float* __restrict__ attn_g, const float* __restrict__ attn_b,
    const float* __restrict__ out_w,  const float* __restrict__ out_b,
    const float* __restrict__ out_g,  const float* __restrict__ out_be,
    const float* __restrict__ wih,    const float* __restrict__ bih)
{
    __shared__ float satt[16 * 64];
    __shared__ float x2[16 * 64];
    __shared__ float ov[16 * 128];
    const int tid = threadIdx.x;
    const int b = blockIdx.x >> 3;
    const int nt0 = (blockIdx.x & 7) * 16;
    const int wid = tid >> 5, lane = tid & 31;

    for (int i = tid; i < 1024; i += 384)
        satt[i] = g_att[(b * NTQ + nt0) * 64 + i];
    __syncthreads();

    if (wid < 8) {
        for (int rr = 0; rr < 2; rr++) {
            int r = wid * 2 + rr;
            float v0 = satt[r * 64 + lane];
            float v1 = satt[r * 64 + lane + 32];
            float mean = wsum(v0 + v1) * (1.0f / 64.0f);
            float d0 = v0 - mean, d1 = v1 - mean;
            float var = wsum(d0 * d0 + d1 * d1) * (1.0f / 64.0f);
            float rs = rsqrtf(var + 1e-5f);
            x2[r * 64 + lane]      = d0 * rs * attn_g[lane]      + attn_b[lane];
            x2[r * 64 + lane + 32] = d1 * rs * attn_g[lane + 32] + attn_b[lane + 32];
        }
    }
    __syncthreads();

    if (tid < 256) {
        int h = tid & 127, half = tid >> 7;
        u64 wo2[32];
        const ulonglong2* wrow = (const ulonglong2*)(out_w + h * 64);
#pragma unroll
        for (int i = 0; i < 16; i++) { ulonglong2 v = wrow[i]; wo2[2 * i] = v.x; wo2[2 * i + 1] = v.y; }
        float ob = out_b[h];
        for (int rr = 0; rr < 8; rr++) {
            int r = half * 8 + rr;
            const ulonglong2* xr = (const ulonglong2*)(x2 + r * 64);
            u64 a0 = 0, a1 = 0;
#pragma unroll
            for (int i = 0; i < 16; i++) {
                ulonglong2 xv = xr[i];
                a0 = ffma2(wo2[2 * i],     xv.x, a0);
                a1 = ffma2(wo2[2 * i + 1], xv.y, a1);
            }
            ov[r * 128 + h] = ob + f2sum(a0) + f2sum(a1);
        }
    }
    __syncthreads();

    if (wid < 8) {
        for (int rr = 0; rr < 2; rr++) {
            int r = wid * 2 + rr;
            float v0 = ov[r * 128 + lane];
            float v1 = ov[r * 128 + lane + 32];
            float v2 = ov[r * 128 + lane + 64];
            float v3 = ov[r * 128 + lane + 96];
            float mean = wsum(v0 + v1 + v2 + v3) * (1.0f / 128.0f);
            float d0 = v0 - mean, d1 = v1 - mean, d2 = v2 - mean, d3 = v3 - mean;
            float var = wsum(d0 * d0 + d1 * d1 + d2 * d2 + d3 * d3) * (1.0f / 128.0f);
            float rs = rsqrtf(var + 1e-5f);
            ov[r * 128 + lane]      = d0 * rs * out_g[lane]      + out_be[lane];
            ov[r * 128 + lane + 32] = d1 * rs * out_g[lane + 32] + out_be[lane + 32];
            ov[r * 128 + lane + 64] = d2 * rs * out_g[lane + 64] + out_be[lane + 64];
            ov[r * 128 + lane + 96] = d3 * rs * out_g[lane + 96] + out_be[lane + 96];
        }
    }
    __syncthreads();

    {
        u64 w2[64];
        const ulonglong2* wrow = (const ulonglong2*)(wih + tid * 128);
#pragma unroll
        for (int i = 0; i < 32; i++) { ulonglong2 v = wrow[i]; w2[2 * i] = v.x; w2[2 * i + 1] = v.y; }
        float bj = bih[tid];
        for (int r = 0; r < 16; r++) {
            const ulonglong2* h2 = (const ulonglong2*)(ov + r * 128);
            u64 a0 = 0, a1 = 0, a2 = 0, a3 = 0;
#pragma unroll
            for (int i = 0; i < 16; i++) {
                ulonglong2 h0 = h2[2 * i], h1 = h2[2 * i + 1];
                a0 = ffma2(w2[4 * i],     h0.x, a0);
                a1 = ffma2(w2[4 * i + 1], h0.y, a1);
                a2 = ffma2(w2[4 * i + 2], h1.x, a2);
                a3 = ffma2(w2[4 * i + 3], h1.y, a3);
            }
            g_gi[(b * NTQ + nt0 + r) * 384 + tid] =
                bj + f2sum(a0) + f2sum(a1) + f2sum(a2) + f2sum(a3);
        }
    }
}

// ---------------------------------------------------------------------------
// Kernel 4: GRU recurrence, 8 blocks (1/batch), 384 threads, FFMA2 matvec.
// ---------------------------------------------------------------------------
__global__ __launch_bounds__(384, 1) void k_gru(
    const float* __restrict__ whh, const float* __restrict__ bhh)
{
    __shared__ float sh[128];
    __shared__ float s1[384];
    __shared__ float sn[128];
    __shared__ float sgn[128];
    const int j = threadIdx.x;
    const int b = blockIdx.x;

    u64 w2[64];
    {
        const ulonglong2* wr = (const ulonglong2*)(whh + j * 128);
#pragma unroll
        for (int i = 0; i < 32; i++) { ulonglong2 v = wr[i]; w2[2 * i] = v.x; w2[2 * i + 1] = v.y; }
    }
    const float bj = bhh[j];
    if (j < 128) sh[j] = 0.f;
    float giv = g_gi[(b * NTQ) * 384 + j];
    __syncthreads();

    for (int t = 0; t < NTQ; t++) {
        const ulonglong2* h2 = (const ulonglong2*)sh;
        u64 a0 = 0, a1 = 0, a2 = 0, a3 = 0;
#pragma unroll
        for (int i = 0; i < 16; i++) {
            ulonglong2 h0 = h2[2 * i], h1 = h2[2 * i + 1];
            a0 = ffma2(w2[4 * i],     h0.x, a0);
            a1 = ffma2(w2[4 * i + 1], h0.y, a1);
            a2 = ffma2(w2[4 * i + 2], h1.x, a2);
            a3 = ffma2(w2[4 * i + 3], h1.y, a3);
        }
        float acc = bj + f2sum(a0) + f2sum(a1) + f2sum(a2) + f2sum(a3);
        float cur = giv;
        if (t + 1 < NTQ) giv = g_gi[(b * NTQ + t + 1) * 384 + j];  // prefetch next step
        s1[j] = acc + cur;
        if (j >= 256) { sn[j - 256] = acc; sgn[j - 256] = cur; }
        __syncthreads();
        if (j < 128) {
            float r = 1.f / (1.f + __expf(-s1[j]));
            float z = 1.f / (1.f + __expf(-s1[j + 128]));
            float n = tanhf(sgn[j] + r * sn[j]);
            sh[j] = (1.f - z) * n + z * sh[j];
        }
        __syncthreads();
    }
    if (j < 128) g_hl[b * 128 + j] = sh[j];
}

// ---------------------------------------------------------------------------
// Kernel 5: classifier MLP -> logits (B, 2)
// ---------------------------------------------------------------------------
__global__ __launch_bounds__(128) void k_cls(
    const float* __restrict__ c1w, const float* __restrict__ c1b,
    const float* __restrict__ c2w, const float* __restrict__ c2b,
    const float* __restrict__ c3w, const float* __restrict__ c3b,
    float* __restrict__ out)
{
    __shared__ float a[128];
    __shared__ float bb[128];
    const int tid = threadIdx.x;
    const int b = blockIdx.x;

    a[tid] = g_hl[b * 128 + tid];
    __syncthreads();
    {
        float acc = c1b[tid];
        const float4* wr = (const float4*)(c1w + tid * 128);
        const float4* h4 = (const float4*)a;
#pragma unroll
        for (int i = 0; i < 32; i++) {
            float4 wv = wr[i]; float4 hv = h4[i];
            acc += hv.x * wv.x + hv.y * wv.y + hv.z * wv.z + hv.w * wv.w;
        }
        bb[tid] = fmaxf(acc, 0.f);
    }
    __syncthreads();
    {
        float acc = c2b[tid];
        const float4* wr = (const float4*)(c2w + tid * 128);
        const float4* h4 = (const float4*)bb;
#pragma unroll
        for (int i = 0; i < 32; i++) {
            float4 wv = wr[i]; float4 hv = h4[i];
            acc += hv.x * wv.x + hv.y * wv.y + hv.z * wv.z + hv.w * wv.w;
        }
        a[tid] = fmaxf(acc, 0.f);
    }
    __syncthreads();
    if (tid < 32) {
        for (int s = 0; s < 2; s++) {
            float p = 0.f;
#pragma unroll
            for (int k = 0; k < 4; k++)
                p += a[tid + 32 * k] * c3w[s * 128 + tid + 32 * k];
            p = wsum(p);
            if (tid == 0) out[b * 2 + s] = p + c3b[s];
        }
    }
}

// ---------------------------------------------------------------------------
extern "C" void kernel_launch(void* const* d_in, const int* in_sizes, int n_in,
                              void* d_out, int out_size)
{
    const float* input      = (const float*)d_in[0];
    const float* mask       = (const float*)d_in[1];
    const float* timesteps  = (const float*)d_in[2];
    const float* periodic_w = (const float*)d_in[3];
    const float* periodic_b = (const float*)d_in[4];
    const float* lin_w      = (const float*)d_in[5];
    const float* lin_b      = (const float*)d_in[6];
    const float* q_w  = (const float*)d_in[7];
    const float* q_b  = (const float*)d_in[8];
    const float* q_g  = (const float*)d_in[9];
    const float* q_be = (const float*)d_in[10];
    const float* k_w  = (const float*)d_in[11];
    const float* k_b  = (const float*)d_in[12];
    const float* k_g  = (const float*)d_in[13];
    const float* k_be = (const float*)d_in[14];
    const float* attn_g = (const float*)d_in[15];
    const float* attn_b = (const float*)d_in[16];
    const float* out_w  = (const float*)d_in[17];
    const float* out_b  = (const float*)d_in[18];
    const float* out_g  = (const float*)d_in[19];
    const float* out_be = (const float*)d_in[20];
    const float* gru_wih = (const float*)d_in[21];
    const float* gru_whh = (const float*)d_in[22];
    const float* gru_bih = (const float*)d_in[23];
    const float* gru_bhh = (const float*)d_in[24];
    const float* c1_w = (const float*)d_in[25];
    const float* c1_b = (const float*)d_in[26];
    const float* c2_w = (const float*)d_in[27];
    const float* c2_b = (const float*)d_in[28];
    const float* c3_w = (const float*)d_in[29];
    const float* c3_b = (const float*)d_in[30];
    float* out = (float*)d_out;

    static bool attr_set = false;
    if (!attr_set) {
        cudaFuncSetAttribute(k_sattn, cudaFuncAttributeMaxDynamicSharedMemorySize, SATTN_SMEM);
        attr_set = true;
    }

    k_embed<<<132, 128>>>(timesteps, periodic_w, periodic_b, lin_w, lin_b,
                          q_w, q_b, q_g, q_be, k_w, k_b, k_g, k_be);
    k_sattn<<<128, 512, SATTN_SMEM>>>(input, mask);
    k_post<<<64, 384>>>(attn_g, attn_b, out_w, out_b, out_g, out_be,
                        gru_wih, gru_bih);
    k_gru<<<8, 384>>>(gru_whh, gru_bhh);
    k_cls<<<8, 128>>>(c1_w, c1_b, c2_w, c2_b, c3_w, c3_b, out);
    (void)in_sizes; (void)n_in; (void)out_size;
}

// round 5
// speedup vs baseline: 1.4762x; 1.1490x over previous
#include <cuda_runtime.h>
#include <math.h>

#define BATCH 8
#define TK    512
#define FDIM  32
#define NTQ   128
#define EDIM  128
#define HDIM  128

typedef unsigned long long u64;

// ---------------- scratch (static device memory; no allocations) ----------------
__device__ float g_q[NTQ * EDIM];
__device__ float g_k[BATCH * TK * EDIM];
__device__ float g_att[BATCH * NTQ * 64];
__device__ float g_gi[BATCH * NTQ * 384];
__device__ float g_hl[BATCH * HDIM];

__device__ __forceinline__ float wsum(float v) {
#pragma unroll
    for (int o = 16; o; o >>= 1) v += __shfl_xor_sync(0xffffffffu, v, o);
    return v;
}
__device__ __forceinline__ float wmax(float v) {
#pragma unroll
    for (int o = 16; o; o >>= 1) v = fmaxf(v, __shfl_xor_sync(0xffffffffu, v, o));
    return v;
}

// packed f32x2 FMA (FFMA2) — 2 MACs per issue slot; PTX-only on sm_103a
__device__ __forceinline__ u64 ffma2(u64 a, u64 b, u64 c) {
    u64 d;
    asm("fma.rn.f32x2 %0, %1, %2, %3;" : "=l"(d) : "l"(a), "l"(b), "l"(c));
    return d;
}
__device__ __forceinline__ u64 fadd2(u64 a, u64 b) {
    u64 d;
    asm("add.rn.f32x2 %0, %1, %2;" : "=l"(d) : "l"(a), "l"(b));
    return d;
}
__device__ __forceinline__ float f2sum(u64 a) {
    float2 v = *(float2*)&a;
    return v.x + v.y;
}
// fast tanh via MUFU.TANH (sm_75+)
__device__ __forceinline__ float tanhapx(float x) {
    float y;
    asm("tanh.approx.f32 %0, %1;" : "=f"(y) : "f"(x));
    return y;
}
// sigmoid(x) = 0.5*tanh(0.5x)+0.5  (1 MUFU + 2 FFMA)
__device__ __forceinline__ float sigapx(float x) {
    return fmaf(tanhapx(0.5f * x), 0.5f, 0.5f);
}

// ---------------------------------------------------------------------------
// Kernel 1: time embedding -> proj -> LN for BOTH q (blocks 0..3) and k (4..131).
// ---------------------------------------------------------------------------
__global__ __launch_bounds__(128) void k_embed(
    const float* __restrict__ times,
    const float* __restrict__ pw, const float* __restrict__ pb,
    const float* __restrict__ lw, const float* __restrict__ lb,
    const float* __restrict__ qW, const float* __restrict__ qbias,
    const float* __restrict__ qg, const float* __restrict__ qbe,
    const float* __restrict__ kW, const float* __restrict__ kbias,
    const float* __restrict__ kg, const float* __restrict__ kbe)
{
    __shared__ float emb[32 * 128];
    __shared__ float pm[32 * 132];
    const int tid = threadIdx.x;
    const bool isQ = blockIdx.x < 4;
    const int r0 = isQ ? blockIdx.x * 32 : (blockIdx.x - 4) * 32;
    float* outp = isQ ? g_q : g_k;
    const float* W     = isQ ? qW : kW;
    const float* bias  = isQ ? qbias : kbias;
    const float* gamma = isQ ? qg : kg;
    const float* beta  = isQ ? qbe : kbe;

    const float lwv = lw[0], lbv = lb[0];
    for (int i = tid; i < 32 * 128; i += 128) {
        int r = i >> 7, e = i & 127;
        float t = isQ ? (float)(r0 + r) * (1.0f / 127.0f) : times[r0 + r];
        float v = (e == 0) ? (t * lwv + lbv) : __sinf(t * pw[e - 1] + pb[e - 1]);
        emb[i] = v;
    }
    __syncthreads();

    u64 w2[64];
    {
        const ulonglong2* wr = (const ulonglong2*)(W + tid * 128);
#pragma unroll
        for (int i = 0; i < 32; i++) { ulonglong2 v = wr[i]; w2[2 * i] = v.x; w2[2 * i + 1] = v.y; }
    }
    const float bv = bias[tid];

    for (int r = 0; r < 32; r++) {
        const ulonglong2* er = (const ulonglong2*)(emb + r * 128);
        u64 a0 = 0, a1 = 0, a2 = 0, a3 = 0;
#pragma unroll
        for (int i = 0; i < 16; i++) {
            ulonglong2 e0 = er[2 * i], e1 = er[2 * i + 1];
            a0 = ffma2(w2[4 * i],     e0.x, a0);
            a1 = ffma2(w2[4 * i + 1], e0.y, a1);
            a2 = ffma2(w2[4 * i + 2], e1.x, a2);
            a3 = ffma2(w2[4 * i + 3], e1.y, a3);
        }
        pm[r * 132 + tid] = bv + f2sum(fadd2(fadd2(a0, a1), fadd2(a2, a3)));
    }
    __syncthreads();

    const int wid = tid >> 5, lane = tid & 31;
    for (int rr = 0; rr < 8; rr++) {
        int r = wid * 8 + rr;
        float v0 = pm[r * 132 + lane];
        float v1 = pm[r * 132 + lane + 32];
        float v2 = pm[r * 132 + lane + 64];
        float v3 = pm[r * 132 + lane + 96];
        float mean = wsum(v0 + v1 + v2 + v3) * (1.0f / 128.0f);
        float d0 = v0 - mean, d1 = v1 - mean, d2 = v2 - mean, d3 = v3 - mean;
        float var = wsum(d0 * d0 + d1 * d1 + d2 * d2 + d3 * d3) * (1.0f / 128.0f);
        float rs = rsqrtf(var + 1e-5f);
        float* orow = outp + (r0 + r) * 128;
        orow[lane]      = d0 * rs * gamma[lane]      + beta[lane];
        orow[lane + 32] = d1 * rs * gamma[lane + 32] + beta[lane + 32];
        orow[lane + 64] = d2 * rs * gamma[lane + 64] + beta[lane + 64];
        orow[lane + 96] = d3 * rs * gamma[lane + 96] + beta[lane + 96];
    }
}

// ---------------------------------------------------------------------------
// Kernel 2: FUSED scores + per-channel masked attention.
// ---------------------------------------------------------------------------
#define SATTN_SMEM ((8 * 128 + 128 * 132 + 8 * 516) * 4)

__global__ __launch_bounds__(512) void k_sattn(
    const float* __restrict__ input, const float* __restrict__ mask)
{
    extern __shared__ float sm[];
    float* sQ = sm;                  // 1024
    float* sK = sQ + 8 * 128;        // 128*132
    float* sE = sK + 128 * 132;      // 8*516

    const int tid = threadIdx.x;
    const int b = blockIdx.x >> 4;
    const int nt0 = (blockIdx.x & 15) * 8;
    const float scale = 0.08838834764831845f;  // 1/sqrt(128)

    if (tid < 256)
        ((float4*)sQ)[tid] = ((const float4*)(g_q + nt0 * 128))[tid];

    const int tl = tid & 127;
    const int ntp = tid >> 7;

    for (int kt = 0; kt < 4; kt++) {
        __syncthreads();
#pragma unroll
        for (int i = 0; i < 8; i++) {
            int idx = tid + i * 512;
            int row = idx >> 5, c4 = idx & 31;
            float4 v = ((const float4*)(g_k + ((b * TK) + kt * 128 + row) * 128))[c4];
            *(float4*)(sK + row * 132 + c4 * 4) = v;
        }
        __syncthreads();

        const ulonglong2* kr = (const ulonglong2*)(sK + tl * 132);
        const ulonglong2* q0 = (const ulonglong2*)(sQ + (ntp * 2) * 128);
        const ulonglong2* q1 = q0 + 32;
        u64 a00 = 0, a01 = 0, a10 = 0, a11 = 0;
#pragma unroll
        for (int i = 0; i < 32; i++) {
            ulonglong2 kv = kr[i];
            ulonglong2 qa = q0[i];
            ulonglong2 qb = q1[i];
            a00 = ffma2(qa.x, kv.x, a00);
            a01 = ffma2(qa.y, kv.y, a01);
            a10 = ffma2(qb.x, kv.x, a10);
            a11 = ffma2(qb.y, kv.y, a11);
        }
        int t = kt * 128 + tl;
        sE[(ntp * 2) * 516 + t]     = f2sum(fadd2(a00, a01)) * scale;
        sE[(ntp * 2 + 1) * 516 + t] = f2sum(fadd2(a10, a11)) * scale;
    }
    __syncthreads();

    {
        int wid = tid >> 5, lane = tid & 31;
        if (wid < 8) {
            float* erow = sE + wid * 516;
            float mx = -1e30f;
#pragma unroll
            for (int k = 0; k < 16; k++) mx = fmaxf(mx, erow[lane + 32 * k]);
            mx = wmax(mx);
#pragma unroll
            for (int k = 0; k < 16; k++) {
                int t = lane + 32 * k;
                erow[t] = __expf(erow[t] - mx);
            }
        }
    }
    __syncthreads();

    const int c = tid >> 4;
    const int nt = (tid >> 1) & 7;
    const int half = tid & 1;
    const float4* mrow = (const float4*)(mask  + (b * FDIM + c) * TK + half * 256);
    const float4* xrow = (const float4*)(input + (b * FDIM + c) * TK + half * 256);
    const float* erow = sE + nt * 516 + half * 256;

    float den = 0.f, num = 0.f;
#pragma unroll 4
    for (int t4 = 0; t4 < 64; t4++) {
        float4 e4 = *(const float4*)(erow + 4 * t4);
        float4 mk = mrow[t4];
        float4 xv = xrow[t4];
        float m0 = (mk.x == 0.f) ? 1.f : 0.f;
        float m1 = (mk.y == 0.f) ? 1.f : 0.f;
        float m2 = (mk.z == 0.f) ? 1.f : 0.f;
        float m3 = (mk.w == 0.f) ? 1.f : 0.f;
        den += e4.x * m0 + e4.y * m1 + e4.z * m2 + e4.w * m3;
        num += e4.x * m0 * xv.x + e4.y * m1 * xv.y + e4.z * m2 * xv.z + e4.w * m3 * xv.w;
    }
    den += __shfl_xor_sync(0xffffffffu, den, 1);
    num += __shfl_xor_sync(0xffffffffu, num, 1);
    if (half == 0) {
        float ax = (den > 0.f) ? (num / den) : 0.f;
        float am = (den > 0.f) ? 1.f : 0.f;
        float* arow = g_att + (b * NTQ + nt0 + nt) * 64;
        arow[c]      = ax;
        arow[c + 32] = am;
    }
}

// ---------------------------------------------------------------------------
// Kernel 3: attn LN -> out proj -> LN -> gi = out @ Wih^T + bih
// ---------------------------------------------------------------------------
__global__ __launch_bounds__(384, 1) void k_post(
    const float* __restrict__ attn_g, const float* __restrict__ attn_b,
    const float* __restrict__ out_w,  const float* __restrict__ out_b,
    const float* __restrict__ out_g,  const float* __restrict__ out_be,
    const float* __restrict__ wih,    const float* __restrict__ bih)
{
    __shared__ float satt[16 * 64];
    __shared__ float x2[16 * 64];
    __shared__ float ov[16 * 128];
    const int tid = threadIdx.x;
    const int b = blockIdx.x >> 3;
    const int nt0 = (blockIdx.x & 7) * 16;
    const int wid = tid >> 5, lane = tid & 31;

    for (int i = tid; i < 1024; i += 384)
        satt[i] = g_att[(b * NTQ + nt0) * 64 + i];
    __syncthreads();

    if (wid < 8) {
        for (int rr = 0; rr < 2; rr++) {
            int r = wid * 2 + rr;
            float v0 = satt[r * 64 + lane];
            float v1 = satt[r * 64 + lane + 32];
            float mean = wsum(v0 + v1) * (1.0f / 64.0f);
            float d0 = v0 - mean, d1 = v1 - mean;
            float var = wsum(d0 * d0 + d1 * d1) * (1.0f / 64.0f);
            float rs = rsqrtf(var + 1e-5f);
            x2[r * 64 + lane]      = d0 * rs * attn_g[lane]      + attn_b[lane];
            x2[r * 64 + lane + 32] = d1 * rs * attn_g[lane + 32] + attn_b[lane + 32];
        }
    }
    __syncthreads();

    if (tid < 256) {
        int h = tid & 127, half = tid >> 7;
        u64 wo2[32];
        const ulonglong2* wrow = (const ulonglong2*)(out_w + h * 64);
#pragma unroll
        for (int i = 0; i < 16; i++) { ulonglong2 v = wrow[i]; wo2[2 * i] = v.x; wo2[2 * i + 1] = v.y; }
        float ob = out_b[h];
        for (int rr = 0; rr < 8; rr++) {
            int r = half * 8 + rr;
            const ulonglong2* xr = (const ulonglong2*)(x2 + r * 64);
            u64 a0 = 0, a1 = 0;
#pragma unroll
            for (int i = 0; i < 16; i++) {
                ulonglong2 xv = xr[i];
                a0 = ffma2(wo2[2 * i],     xv.x, a0);
                a1 = ffma2(wo2[2 * i + 1], xv.y, a1);
            }
            ov[r * 128 + h] = ob + f2sum(fadd2(a0, a1));
        }
    }
    __syncthreads();

    if (wid < 8) {
        for (int rr = 0; rr < 2; rr++) {
            int r = wid * 2 + rr;
            float v0 = ov[r * 128 + lane];
            float v1 = ov[r * 128 + lane + 32];
            float v2 = ov[r * 128 + lane + 64];
            float v3 = ov[r * 128 + lane + 96];
            float mean = wsum(v0 + v1 + v2 + v3) * (1.0f / 128.0f);
            float d0 = v0 - mean, d1 = v1 - mean, d2 = v2 - mean, d3 = v3 - mean;
            float var = wsum(d0 * d0 + d1 * d1 + d2 * d2 + d3 * d3) * (1.0f / 128.0f);
            float rs = rsqrtf(var + 1e-5f);
            ov[r * 128 + lane]      = d0 * rs * out_g[lane]      + out_be[lane];
            ov[r * 128 + lane + 32] = d1 * rs * out_g[lane + 32] + out_be[lane + 32];
            ov[r * 128 + lane + 64] = d2 * rs * out_g[lane + 64] + out_be[lane + 64];
            ov[r * 128 + lane + 96] = d3 * rs * out_g[lane + 96] + out_be[lane + 96];
        }
    }
    __syncthreads();

    {
        u64 w2[64];
        const ulonglong2* wrow = (const ulonglong2*)(wih + tid * 128);
#pragma unroll
        for (int i = 0; i < 32; i++) { ulonglong2 v = wrow[i]; w2[2 * i] = v.x; w2[2 * i + 1] = v.y; }
        float bj = bih[tid];
        for (int r = 0; r < 16; r++) {
            const ulonglong2* h2 = (const ulonglong2*)(ov + r * 128);
            u64 a0 = 0, a1 = 0, a2 = 0, a3 = 0;
#pragma unroll
            for (int i = 0; i < 16; i++) {
                ulonglong2 h0 = h2[2 * i], h1 = h2[2 * i + 1];
                a0 = ffma2(w2[4 * i],     h0.x, a0);
                a1 = ffma2(w2[4 * i + 1], h0.y, a1);
                a2 = ffma2(w2[4 * i + 2], h1.x, a2);
                a3 = ffma2(w2[4 * i + 3], h1.y, a3);
            }
            g_gi[(b * NTQ + nt0 + r) * 384 + tid] =
                bj + f2sum(fadd2(fadd2(a0, a1), fadd2(a2, a3)));
        }
    }
}

// ---------------------------------------------------------------------------
// Kernel 4: GRU recurrence, 8 blocks (1/batch), 384 threads, FFMA2 matvec.
// Gate nonlinearities via MUFU.TANH (tanh.approx) — no libm in the hot loop.
// ---------------------------------------------------------------------------
__global__ __launch_bounds__(384, 1) void k_gru(
    const float* __restrict__ whh, const float* __restrict__ bhh)
{
    __shared__ float sh[128];
    __shared__ float s1[384];
    __shared__ float sn[128];
    __shared__ float sgn[128];
    const int j = threadIdx.x;
    const int b = blockIdx.x;

    u64 w2[64];
    {
        const ulonglong2* wr = (const ulonglong2*)(whh + j * 128);
#pragma unroll
        for (int i = 0; i < 32; i++) { ulonglong2 v = wr[i]; w2[2 * i] = v.x; w2[2 * i + 1] = v.y; }
    }
    const float bj = bhh[j];
    if (j < 128) sh[j] = 0.f;
    float giv = g_gi[(b * NTQ) * 384 + j];
    __syncthreads();

    for (int t = 0; t < NTQ; t++) {
        const ulonglong2* h2 = (const ulonglong2*)sh;
        u64 a0 = 0, a1 = 0, a2 = 0, a3 = 0;
#pragma unroll
        for (int i = 0; i < 16; i++) {
            ulonglong2 h0 = h2[2 * i], h1 = h2[2 * i + 1];
            a0 = ffma2(w2[4 * i],     h0.x, a0);
            a1 = ffma2(w2[4 * i + 1], h0.y, a1);
            a2 = ffma2(w2[4 * i + 2], h1.x, a2);
            a3 = ffma2(w2[4 * i + 3], h1.y, a3);
        }
        float acc = bj + f2sum(fadd2(fadd2(a0, a1), fadd2(a2, a3)));
        float cur = giv;
        if (t + 1 < NTQ) giv = g_gi[(b * NTQ + t + 1) * 384 + j];  // prefetch next step
        s1[j] = acc + cur;
        if (j >= 256) { sn[j - 256] = acc; sgn[j - 256] = cur; }
        __syncthreads();
        if (j < 128) {
            float r = sigapx(s1[j]);
            float z = sigapx(s1[j + 128]);
            float n = tanhapx(fmaf(r, sn[j], sgn[j]));
            sh[j] = fmaf(z, sh[j] - n, n);
        }
        __syncthreads();
    }
    if (j < 128) g_hl[b * 128 + j] = sh[j];
}

// ---------------------------------------------------------------------------
// Kernel 5: classifier MLP -> logits (B, 2)
// ---------------------------------------------------------------------------
__global__ __launch_bounds__(128) void k_cls(
    const float* __restrict__ c1w, const float* __restrict__ c1b,
    const float* __restrict__ c2w, const float* __restrict__ c2b,
    const float* __restrict__ c3w, const float* __restrict__ c3b,
    float* __restrict__ out)
{
    __shared__ float a[128];
    __shared__ float bb[128];
    const int tid = threadIdx.x;
    const int b = blockIdx.x;

    a[tid] = g_hl[b * 128 + tid];
    __syncthreads();
    {
        float acc = c1b[tid];
        const float4* wr = (const float4*)(c1w + tid * 128);
        const float4* h4 = (const float4*)a;
#pragma unroll
        for (int i = 0; i < 32; i++) {
            float4 wv = wr[i]; float4 hv = h4[i];
            acc += hv.x * wv.x + hv.y * wv.y + hv.z * wv.z + hv.w * wv.w;
        }
        bb[tid] = fmaxf(acc, 0.f);
    }
    __syncthreads();
    {
        float acc = c2b[tid];
        const float4* wr = (const float4*)(c2w + tid * 128);
        const float4* h4 = (const float4*)bb;
#pragma unroll
        for (int i = 0; i < 32; i++) {
            float4 wv = wr[i]; float4 hv = h4[i];
            acc += hv.x * wv.x + hv.y * wv.y + hv.z * wv.z + hv.w * wv.w;
        }
        a[tid] = fmaxf(acc, 0.f);
    }
    __syncthreads();
    if (tid < 32) {
        for (int s = 0; s < 2; s++) {
            float p = 0.f;
#pragma unroll
            for (int k = 0; k < 4; k++)
                p += a[tid + 32 * k] * c3w[s * 128 + tid + 32 * k];
            p = wsum(p);
            if (tid == 0) out[b * 2 + s] = p + c3b[s];
        }
    }
}

// ---------------------------------------------------------------------------
extern "C" void kernel_launch(void* const* d_in, const int* in_sizes, int n_in,
                              void* d_out, int out_size)
{
    const float* input      = (const float*)d_in[0];
    const float* mask       = (const float*)d_in[1];
    const float* timesteps  = (const float*)d_in[2];
    const float* periodic_w = (const float*)d_in[3];
    const float* periodic_b = (const float*)d_in[4];
    const float* lin_w      = (const float*)d_in[5];
    const float* lin_b      = (const float*)d_in[6];
    const float* q_w  = (const float*)d_in[7];
    const float* q_b  = (const float*)d_in[8];
    const float* q_g  = (const float*)d_in[9];
    const float* q_be = (const float*)d_in[10];
    const float* k_w  = (const float*)d_in[11];
    const float* k_b  = (const float*)d_in[12];
    const float* k_g  = (const float*)d_in[13];
    const float* k_be = (const float*)d_in[14];
    const float* attn_g = (const float*)d_in[15];
    const float* attn_b = (const float*)d_in[16];
    const float* out_w  = (const float*)d_in[17];
    const float* out_b  = (const float*)d_in[18];
    const float* out_g  = (const float*)d_in[19];
    const float* out_be = (const float*)d_in[20];
    const float* gru_wih = (const float*)d_in[21];
    const float* gru_whh = (const float*)d_in[22];
    const float* gru_bih = (const float*)d_in[23];
    const float* gru_bhh = (const float*)d_in[24];
    const float* c1_w = (const float*)d_in[25];
    const float* c1_b = (const float*)d_in[26];
    const float* c2_w = (const float*)d_in[27];
    const float* c2_b = (const float*)d_in[28];
    const float* c3_w = (const float*)d_in[29];
    const float* c3_b = (const float*)d_in[30];
    float* out = (float*)d_out;

    static bool attr_set = false;
    if (!attr_set) {
        cudaFuncSetAttribute(k_sattn, cudaFuncAttributeMaxDynamicSharedMemorySize, SATTN_SMEM);
        attr_set = true;
    }

    k_embed<<<132, 128>>>(timesteps, periodic_w, periodic_b, lin_w, lin_b,
                          q_w, q_b, q_g, q_be, k_w, k_b, k_g, k_be);
    k_sattn<<<128, 512, SATTN_SMEM>>>(input, mask);
    k_post<<<64, 384>>>(attn_g, attn_b, out_w, out_b, out_g, out_be,
                        gru_wih, gru_bih);
    k_gru<<<8, 384>>>(gru_whh, gru_bhh);
    k_cls<<<8, 128>>>(c1_w, c1_b, c2_w, c2_b, c3_w, c3_b, out);
    (void)in_sizes; (void)n_in; (void)out_size;
}